// round 12
// baseline (speedup 1.0000x reference)
#include <cuda_runtime.h>
#include <cuda_bf16.h>

// PointPillarsScatter gather v11 (v8 skeleton, 8 cells x 2 channels per thread):
//  - d_cellinfo[cell] = (n<<24) | sum(pid); n==1 (94.5% of occupied) pid is embedded
//  - thread covers 8 consecutive cells (32B cellinfo = ONE sector round-trip) x 2 ch
//    -> mandatory-latency events per cell halved vs v8; feats loads are independent
//  - warp: 1KB contiguous cellinfo reads, 1KB contiguous stores per channel (STG.128 __stcs)
//  - build: 2 pillars/thread via int4 coord loads (MLP 2 on the atomic chain)
//
// Inputs:
//   d_in[0]: pillar_feats  float32 [B=4, P=30000, C=64]
//   d_in[1]: pillar_coords int32   [B=4, P=30000, 2]  (y, x)
// Output: float32 [4, 64, 512, 512]

#define BEV_H 512
#define BEV_W 512
#define HW (BEV_H * BEV_W)       // 262144 = 2^18
#define C_DIM 64
#define P_DIM 30000
#define B_DIM 4
#define CAP 8
#define NBLK ((B_DIM * HW) / 8)  // 131072 groups of 8 cells

__device__ unsigned int   d_cellinfo[B_DIM * HW];     // 4 MB: (count<<24) | sum(pid)
__device__ unsigned short d_list[B_DIM * HW * CAP];   // 16 MB side lists (n>=2 only)

__global__ void pp_build_kernel(const int* __restrict__ coords) {
    int t = blockIdx.x * blockDim.x + threadIdx.x;
    if (t >= (B_DIM * P_DIM) / 2) return;

    // Two pillars per thread: one int4 = {y0,x0,y1,x1}
    int4 cc = reinterpret_cast<const int4*>(coords)[t];

    int p0 = 2 * t, p1 = 2 * t + 1;

    int y0 = min(max(cc.x, 0), BEV_H - 1);
    int x0 = min(max(cc.y, 0), BEV_W - 1);
    int y1 = min(max(cc.z, 0), BEV_H - 1);
    int x1 = min(max(cc.w, 0), BEV_W - 1);

    int b0 = p0 / P_DIM, b1 = p1 / P_DIM;
    int pid0 = p0 - b0 * P_DIM, pid1 = p1 - b1 * P_DIM;
    int idx0 = b0 * HW + y0 * BEV_W + x0;
    int idx1 = b1 * HW + y1 * BEV_W + x1;

    unsigned old0 = atomicAdd(&d_cellinfo[idx0], (1u << 24) | (unsigned)pid0);
    unsigned old1 = atomicAdd(&d_cellinfo[idx1], (1u << 24) | (unsigned)pid1);
    unsigned pos0 = old0 >> 24, pos1 = old1 >> 24;
    if (pos0 < CAP) d_list[(size_t)idx0 * CAP + pos0] = (unsigned short)pid0;
    if (pos1 < CAP) d_list[(size_t)idx1 * CAP + pos1] = (unsigned short)pid1;
}

__global__ __launch_bounds__(256) void pp_gather_kernel(const float* __restrict__ feats,
                                                        float* __restrict__ out) {
    int tid = blockIdx.x * blockDim.x + threadIdx.x;  // 0 .. 32*NBLK
    int grp = tid & (NBLK - 1);     // 8-cell group (consecutive across warp)
    int chg = tid >> 17;            // channel pair 0..31

    int idx0  = grp << 3;           // first cell index (b*HW + cell)
    int b     = idx0 >> 18;
    int cell0 = idx0 & (HW - 1);

    // 32B of cellinfo: two adjacent uint4 loads, same 32B sector -> one round-trip
    const uint4* info = reinterpret_cast<const uint4*>(&d_cellinfo[idx0]);
    uint4 wv0 = info[0];
    uint4 wv1 = info[1];
    unsigned w[8] = {wv0.x, wv0.y, wv0.z, wv0.w, wv1.x, wv1.y, wv1.z, wv1.w};

    float2 acc[8];
    #pragma unroll
    for (int ci = 0; ci < 8; ci++) acc[ci] = make_float2(0.f, 0.f);

    const float* fb = feats + (size_t)b * P_DIM * C_DIM + (chg << 1);

    #pragma unroll
    for (int ci = 0; ci < 8; ci++) {
        unsigned n = w[ci] >> 24;
        if (n == 0) continue;                    // ~89% of cells
        if (n == 1) {                            // pid embedded in the word
            unsigned pid = w[ci] & 0xFFFFFFu;
            float2 v = *reinterpret_cast<const float2*>(fb + (size_t)pid * C_DIM);
            acc[ci].x += v.x; acc[ci].y += v.y;
        } else {                                 // rare (0.65%): side list
            int m = min((int)n, CAP);
            const unsigned short* lst = &d_list[(size_t)(idx0 + ci) * CAP];
            for (int i = 0; i < m; i++) {
                unsigned pid = lst[i];
                float2 v = *reinterpret_cast<const float2*>(fb + (size_t)pid * C_DIM);
                acc[ci].x += v.x; acc[ci].y += v.y;
            }
        }
    }

    // Two channels, 8 consecutive cells each: 2 x STG.128 per channel
    float* o = out + ((size_t)b * C_DIM + (size_t)(chg << 1)) * HW + cell0;
    __stcs(reinterpret_cast<float4*>(o),
           make_float4(acc[0].x, acc[1].x, acc[2].x, acc[3].x));
    __stcs(reinterpret_cast<float4*>(o + 4),
           make_float4(acc[4].x, acc[5].x, acc[6].x, acc[7].x));
    __stcs(reinterpret_cast<float4*>(o + HW),
           make_float4(acc[0].y, acc[1].y, acc[2].y, acc[3].y));
    __stcs(reinterpret_cast<float4*>(o + HW + 4),
           make_float4(acc[4].y, acc[5].y, acc[6].y, acc[7].y));
}

extern "C" void kernel_launch(void* const* d_in, const int* in_sizes, int n_in,
                              void* d_out, int out_size) {
    const float* feats  = (const float*)d_in[0];
    const int*   coords = (const int*)d_in[1];
    float*       out    = (float*)d_out;

    // Zero the fused cell words (4 MB, graph-capturable)
    void* info_ptr = nullptr;
    cudaGetSymbolAddress(&info_ptr, d_cellinfo);
    cudaMemsetAsync(info_ptr, 0, (size_t)B_DIM * HW * sizeof(unsigned int));

    int n_pairs = (B_DIM * P_DIM) / 2;             // 60,000 threads, 2 pillars each
    pp_build_kernel<<<(n_pairs + 255) / 256, 256>>>(coords);

    int n_threads = 32 * NBLK;                     // 4,194,304
    pp_gather_kernel<<<n_threads / 256, 256>>>(feats, out);
}

// round 13
// speedup vs baseline: 1.4029x; 1.4029x over previous
#include <cuda_runtime.h>
#include <cuda_bf16.h>

// PointPillarsScatter gather v12 (v8 skeleton + lean predicated body + 32-reg cap):
//  - d_cellinfo[cell] = (n<<24) | sum(pid); n==1 pid embedded (94.5% of occupied)
//  - hot path: predicated float4 feats load per cell, straight into store regs
//  - n>=2 (0.65% of cells): inline rare fixup block (regs reused, no extra kernel)
//  - __launch_bounds__(256, 8) caps regs at 32 -> 64-warp occupancy ceiling (+33% vs v8)
//  - build: 2 pillars/thread via int4 coord loads
//
// Inputs:
//   d_in[0]: pillar_feats  float32 [B=4, P=30000, C=64]
//   d_in[1]: pillar_coords int32   [B=4, P=30000, 2]  (y, x)
// Output: float32 [4, 64, 512, 512]

#define BEV_H 512
#define BEV_W 512
#define HW (BEV_H * BEV_W)      // 262144 = 2^18
#define C_DIM 64
#define P_DIM 30000
#define B_DIM 4
#define CAP 8
#define NGRP ((B_DIM * HW) / 4) // 262144 groups of 4 cells

__device__ unsigned int   d_cellinfo[B_DIM * HW];     // 4 MB: (count<<24) | sum(pid)
__device__ unsigned short d_list[B_DIM * HW * CAP];   // 16 MB side lists (n>=2 only)

__global__ void pp_build_kernel(const int* __restrict__ coords) {
    int t = blockIdx.x * blockDim.x + threadIdx.x;
    if (t >= (B_DIM * P_DIM) / 2) return;

    int4 cc = reinterpret_cast<const int4*>(coords)[t];   // {y0,x0,y1,x1}
    int p0 = 2 * t, p1 = 2 * t + 1;

    int y0 = min(max(cc.x, 0), BEV_H - 1);
    int x0 = min(max(cc.y, 0), BEV_W - 1);
    int y1 = min(max(cc.z, 0), BEV_H - 1);
    int x1 = min(max(cc.w, 0), BEV_W - 1);

    int b0 = p0 / P_DIM, b1 = p1 / P_DIM;
    int pid0 = p0 - b0 * P_DIM, pid1 = p1 - b1 * P_DIM;
    int idx0 = b0 * HW + y0 * BEV_W + x0;
    int idx1 = b1 * HW + y1 * BEV_W + x1;

    unsigned old0 = atomicAdd(&d_cellinfo[idx0], (1u << 24) | (unsigned)pid0);
    unsigned old1 = atomicAdd(&d_cellinfo[idx1], (1u << 24) | (unsigned)pid1);
    unsigned pos0 = old0 >> 24, pos1 = old1 >> 24;
    if (pos0 < CAP) d_list[(size_t)idx0 * CAP + pos0] = (unsigned short)pid0;
    if (pos1 < CAP) d_list[(size_t)idx1 * CAP + pos1] = (unsigned short)pid1;
}

__global__ __launch_bounds__(256, 8) void pp_gather_kernel(const float* __restrict__ feats,
                                                           float* __restrict__ out) {
    int tid = blockIdx.x * blockDim.x + threadIdx.x;  // 0 .. 16*NGRP
    int grp = tid & (NGRP - 1);     // cell group (consecutive across warp -> coalesced)
    int chg = tid >> 18;            // channel group 0..15 (4 channels each)

    int idx0  = grp << 2;
    int b     = idx0 >> 18;
    int cell0 = idx0 & (HW - 1);

    // One coalesced 16B load: count|pid for 4 cells (4MB, L2-resident)
    uint4 wv = *reinterpret_cast<const uint4*>(&d_cellinfo[idx0]);
    unsigned w[4] = {wv.x, wv.y, wv.z, wv.w};

    const float* fb = feats + (size_t)b * P_DIM * C_DIM + (chg << 2);

    // Hot path: predicated n==1 load directly into the store registers.
    float4 a[4];
    #pragma unroll
    for (int ci = 0; ci < 4; ci++) {
        float4 v = make_float4(0.f, 0.f, 0.f, 0.f);
        if ((w[ci] >> 24) == 1) {
            unsigned pid = w[ci] & 0xFFFFFFu;
            v = *reinterpret_cast<const float4*>(fb + (size_t)pid * C_DIM);
        }
        a[ci] = v;
    }

    // Rare path (0.65% of cells): inline multi-pillar sum from the side list.
    if (((w[0] | w[1] | w[2] | w[3]) >> 24) > 1) {
        #pragma unroll
        for (int ci = 0; ci < 4; ci++) {
            int n = (int)(w[ci] >> 24);
            if (n < 2) continue;
            n = min(n, CAP);
            float4 s = make_float4(0.f, 0.f, 0.f, 0.f);
            const unsigned short* lst = &d_list[(size_t)(idx0 + ci) * CAP];
            for (int i = 0; i < n; i++) {
                float4 v = *reinterpret_cast<const float4*>(fb + (size_t)lst[i] * C_DIM);
                s.x += v.x; s.y += v.y; s.z += v.z; s.w += v.w;
            }
            a[ci] = s;
        }
    }

    float* o = out + ((size_t)b * C_DIM + (size_t)(chg << 2)) * HW + cell0;
    __stcs(reinterpret_cast<float4*>(o + 0 * (size_t)HW), make_float4(a[0].x, a[1].x, a[2].x, a[3].x));
    __stcs(reinterpret_cast<float4*>(o + 1 * (size_t)HW), make_float4(a[0].y, a[1].y, a[2].y, a[3].y));
    __stcs(reinterpret_cast<float4*>(o + 2 * (size_t)HW), make_float4(a[0].z, a[1].z, a[2].z, a[3].z));
    __stcs(reinterpret_cast<float4*>(o + 3 * (size_t)HW), make_float4(a[0].w, a[1].w, a[2].w, a[3].w));
}

extern "C" void kernel_launch(void* const* d_in, const int* in_sizes, int n_in,
                              void* d_out, int out_size) {
    const float* feats  = (const float*)d_in[0];
    const int*   coords = (const int*)d_in[1];
    float*       out    = (float*)d_out;

    // Zero the fused cell words (4 MB, graph-capturable)
    void* info_ptr = nullptr;
    cudaGetSymbolAddress(&info_ptr, d_cellinfo);
    cudaMemsetAsync(info_ptr, 0, (size_t)B_DIM * HW * sizeof(unsigned int));

    int n_pairs = (B_DIM * P_DIM) / 2;             // 60,000 threads, 2 pillars each
    pp_build_kernel<<<(n_pairs + 255) / 256, 256>>>(coords);

    int n_threads = 16 * NGRP;                     // 4,194,304
    pp_gather_kernel<<<n_threads / 256, 256>>>(feats, out);
}